// round 15
// baseline (speedup 1.0000x reference)
#include <cuda_runtime.h>
#include <cuda_fp16.h>
#include <cstdint>

// ============================================================================
// ModelR: x[8192,1024] -> (Linear+LeakyReLU) x4 -> Linear -> tri-scatter
// Round 15: BK 64->128 (half the stage/barrier count; per-stage fixed cost
// amortized over 2x MMA work). BM=128, BN=256, warp tile 64x64, 2-stage
// cp.async. Stage = (128+256) rows x 272B = 104448B; 208896B total smem.
// PITCH 272B = 68 words = 4 mod 32 banks -> same conflict-free ldsm as 144.
// K-accumulation order unchanged => rel_err expected bitwise 6.548771e-4.
// ============================================================================

#define BATCH 8192
#define DIN   1024
#define HID   2048
#define LOUT  2080
#define CPV   64

#define PITCH   272         // 256B payload (128 fp16) + 16B pad
#define OFF_A   0
#define OFF_B   34816       // 128 rows * 272B
#define STAGE   104448      // + 256 rows * 272B
#define NSTAGE  2
#define SMEMSZ  (NSTAGE * STAGE)   // 208896 B

// ------------------------- device scratch (no allocs) -----------------------
__device__ __half g_A0[(size_t)BATCH * HID];
__device__ __half g_A1[(size_t)BATCH * HID];
__device__ __half g_W1t[(size_t)HID * DIN];
__device__ __half g_W2t[(size_t)HID * HID];
__device__ __half g_W21t[(size_t)HID * HID];
__device__ __half g_W22t[(size_t)HID * HID];
__device__ __half g_W3t[(size_t)LOUT * HID];
__device__ float  g_Y[(size_t)BATCH * LOUT];

// ------------------------------ PTX helpers ---------------------------------
__device__ __forceinline__ uint32_t smem_u32(const void* p) {
    uint32_t a;
    asm("{ .reg .u64 t; cvta.to.shared.u64 t, %1; cvt.u32.u64 %0, t; }"
        : "=r"(a) : "l"(p));
    return a;
}
__device__ __forceinline__ void cp16(uint32_t d, const void* s, int sz) {
    asm volatile("cp.async.cg.shared.global [%0], [%1], 16, %2;"
                 :: "r"(d), "l"(s), "r"(sz) : "memory");
}
__device__ __forceinline__ void cp_commit() {
    asm volatile("cp.async.commit_group;" ::: "memory");
}
template <int N> __device__ __forceinline__ void cp_wait() {
    asm volatile("cp.async.wait_group %0;" :: "n"(N) : "memory");
}
__device__ __forceinline__ void ldsm4(uint32_t* r, uint32_t a) {
    asm volatile("ldmatrix.sync.aligned.m8n8.x4.shared.b16 {%0,%1,%2,%3}, [%4];"
                 : "=r"(r[0]), "=r"(r[1]), "=r"(r[2]), "=r"(r[3]) : "r"(a));
}
__device__ __forceinline__ void mma16816(float* d, const uint32_t* a,
                                         const uint32_t* b) {
    asm volatile(
        "mma.sync.aligned.m16n8k16.row.col.f32.f16.f16.f32 "
        "{%0,%1,%2,%3}, {%4,%5,%6,%7}, {%8,%9}, {%0,%1,%2,%3};"
        : "+f"(d[0]), "+f"(d[1]), "+f"(d[2]), "+f"(d[3])
        : "r"(a[0]), "r"(a[1]), "r"(a[2]), "r"(a[3]), "r"(b[0]), "r"(b[1]));
}

// ------------------------------- GEMM kernel --------------------------------
// D[M, Ntot] = A[M,K] @ B[Ntot,K]^T + bias; optional lrelu.
// BM=128, BN=256, BK=128. 8 warps: warp tile 64x64 (warp_m 2 x warp_n 4).
__global__ void __launch_bounds__(256, 1)
gemm_f16(const __half* __restrict__ A, const __half* __restrict__ B,
         const float* __restrict__ bias,
         __half* __restrict__ Cout, float* __restrict__ Yout,
         int K, int Ntot, int act, int f32out)
{
    extern __shared__ char sm[];
    const uint32_t sbase = smem_u32(sm);

    const int tid  = threadIdx.x;
    const int wid  = tid >> 5;
    const int lane = tid & 31;
    const int warp_m = wid & 1;        // 2 x 64 rows
    const int warp_n = wid >> 1;       // 4 x 64 cols
    const int m0 = blockIdx.y * 128;
    const int n0 = blockIdx.x * 256;

    float acc[4][8][4];
#pragma unroll
    for (int i = 0; i < 4; i++)
#pragma unroll
        for (int j = 0; j < 8; j++)
#pragma unroll
            for (int k = 0; k < 4; k++) acc[i][j][k] = 0.f;

    const int kn = K >> 7;             // BK = 128

    // ldmatrix per-lane offsets (bytes, within a stage)
    const uint32_t a_off = (uint32_t)((warp_m * 64 + (lane & 15)) * PITCH
                                      + (lane >> 4) * 16);
    const uint32_t b_off = (uint32_t)((warp_n * 64 + (lane & 7) + ((lane >> 4) << 3)) * PITCH
                                      + ((lane >> 3) & 1) * 16);

    // cp.async: A tile 128 rows x 16 chunks = 2048 -> 8/thread;
    //           B tile 256 rows x 16 chunks = 4096 -> 16/thread.
#define LOAD_STAGE(KS, BUF)                                                          \
    {                                                                                \
        const int k0_ = (KS) << 7;                                                   \
        const uint32_t sb_ = sbase + (BUF) * STAGE;                                  \
        _Pragma("unroll")                                                            \
        for (int j_ = 0; j_ < 8; j_++) {                                             \
            int slot_ = tid + j_ * 256;                                              \
            int row_ = slot_ >> 4;                                                   \
            int col_ = slot_ & 15;                                                   \
            uint32_t d_ = sb_ + (uint32_t)(row_ * PITCH + col_ * 16);                \
            size_t ga_ = (size_t)(m0 + row_) * K + k0_ + col_ * 8;                   \
            cp16(d_ + OFF_A, A + ga_, 16);                                           \
        }                                                                            \
        _Pragma("unroll")                                                            \
        for (int j_ = 0; j_ < 16; j_++) {                                            \
            int slot_ = tid + j_ * 256;                                              \
            int row_ = slot_ >> 4;                                                   \
            int col_ = slot_ & 15;                                                   \
            uint32_t d_ = sb_ + (uint32_t)(row_ * PITCH + col_ * 16);                \
            int n_ = n0 + row_;                                                      \
            int sz_ = (n_ < Ntot) ? 16 : 0;                                          \
            int nc_ = (n_ < Ntot) ? n_ : (Ntot - 1);                                 \
            size_t gb_ = (size_t)nc_ * K + k0_ + col_ * 8;                           \
            cp16(d_ + OFF_B, B + gb_, sz_);                                          \
        }                                                                            \
    }

    LOAD_STAGE(0, 0); cp_commit();

    for (int ks = 0; ks < kn; ks++) {
        if (ks + 1 < kn) {
            LOAD_STAGE(ks + 1, (ks + 1) & 1); cp_commit(); cp_wait<1>();
        } else {
            cp_wait<0>();
        }
        __syncthreads();

        const uint32_t sb = sbase + (ks & 1) * STAGE;
#pragma unroll
        for (int kk = 0; kk < 8; kk++) {           // 8 x K16 per stage
            uint32_t ah[4][4];
#pragma unroll
            for (int mt = 0; mt < 4; mt++) {
                uint32_t o = a_off + (uint32_t)(mt * 16 * PITCH + kk * 32);
                ldsm4(ah[mt], sb + OFF_A + o);
            }
#pragma unroll
            for (int np = 0; np < 4; np++) {       // 4 x 16-col B panels
                uint32_t o = b_off + (uint32_t)(np * 16 * PITCH + kk * 32);
                uint32_t r[4];
                ldsm4(r, sb + OFF_B + o);
#pragma unroll
                for (int mt = 0; mt < 4; mt++) {
                    mma16816(acc[mt][2 * np],     ah[mt], r);
                    mma16816(acc[mt][2 * np + 1], ah[mt], r + 2);
                }
            }
        }
        if (ks + 1 < kn) __syncthreads();   // protect buf before next overwrite
    }

    // ---- epilogue: bias + act, write fp16 or fp32 ----
    const int mrow = lane >> 2;
    const int ncol = (lane & 3) * 2;
#pragma unroll
    for (int mt = 0; mt < 4; mt++) {
#pragma unroll
        for (int nt = 0; nt < 8; nt++) {
            int n = n0 + warp_n * 64 + nt * 8 + ncol;
            if (n >= Ntot) continue;
            float bs0 = __ldg(bias + n);
            float bs1 = __ldg(bias + n + 1);
#pragma unroll
            for (int half_ = 0; half_ < 2; half_++) {
                int m = m0 + warp_m * 64 + mt * 16 + mrow + half_ * 8;
                float v0 = acc[mt][nt][half_ * 2]     + bs0;
                float v1 = acc[mt][nt][half_ * 2 + 1] + bs1;
                if (act) {
                    v0 = v0 > 0.f ? v0 : 0.01f * v0;
                    v1 = v1 > 0.f ? v1 : 0.01f * v1;
                }
                if (f32out) {
                    *(float2*)(Yout + (size_t)m * Ntot + n) = make_float2(v0, v1);
                } else {
                    *(__half2*)(Cout + (size_t)m * Ntot + n) =
                        __halves2half2(__float2half_rn(v0), __float2half_rn(v1));
                }
            }
        }
    }
}

// --------------------------- cast / transpose -------------------------------
// x fp32 -> fp16 (float4-vectorized)
__global__ void cast_f32_f16(const float* __restrict__ in,
                             __half* __restrict__ out, int n4)
{
    int i = blockIdx.x * blockDim.x + threadIdx.x;
    if (i < n4) {
        float4 v = ((const float4*)in)[i];
        ((__half2*)out)[i * 2]     = __halves2half2(__float2half_rn(v.x), __float2half_rn(v.y));
        ((__half2*)out)[i * 2 + 1] = __halves2half2(__float2half_rn(v.z), __float2half_rn(v.w));
    }
}

// W[K,N] fp32 -> BT[N,K] fp16 (transpose). Dims %32 == 0.
__global__ void wsplit_t_kernel(const float* __restrict__ W,
                                __half* __restrict__ bt, int K, int N)
{
    __shared__ float t[32][33];
    const int n0 = blockIdx.x * 32, k0 = blockIdx.y * 32;
    const int tx = threadIdx.x, ty = threadIdx.y;
#pragma unroll
    for (int i = 0; i < 32; i += 8)
        t[ty + i][tx] = W[(size_t)(k0 + ty + i) * N + n0 + tx];
    __syncthreads();
#pragma unroll
    for (int i = 0; i < 32; i += 8) {
        float v = t[tx][ty + i];                 // element (k0+tx, n0+ty+i)
        bt[(size_t)(n0 + ty + i) * K + k0 + tx] = __float2half_rn(v);
    }
}

// ------------------------------- scatter ------------------------------------
// Writes upper-tri values AND mirrored lower-tri zeros (no separate memset).
__global__ void scatter_tri(const float* __restrict__ y, float* __restrict__ out)
{
    __shared__ float tile[32][33];
    const int l0 = blockIdx.x * 32;
    const int b0 = blockIdx.y * 32;
    const int txi = threadIdx.x;
    const int tyi = threadIdx.y;

#pragma unroll
    for (int i = 0; i < 32; i += 8)
        tile[tyi + i][txi] = y[(size_t)(b0 + tyi + i) * LOUT + l0 + txi];
    __syncthreads();

#pragma unroll
    for (int i = 0; i < 32; i += 8) {
        int l = l0 + tyi + i;
        float disc = 16641.0f - 8.0f * (float)l;
        int r = (int)((129.0f - sqrtf(disc)) * 0.5f);
        if (r < 0) r = 0;
        if (r > 63) r = 63;
        while (r < 63 && (r + 1) * (129 - (r + 1)) / 2 <= l) r++;
        while (r > 0 && r * (129 - r) / 2 > l) r--;
        int c = 63 - (l - r * (129 - r) / 2);
        float v = tile[txi][tyi + i];            // transposed read
        if (r == c && v <= 0.f) v = -v;
        out[((size_t)(r * CPV + c)) * BATCH + b0 + txi] = v;
        if (r != c)                              // mirrored zero (lower tri)
            out[((size_t)(c * CPV + r)) * BATCH + b0 + txi] = 0.f;
    }
}

// ------------------------------- launcher -----------------------------------
extern "C" void kernel_launch(void* const* d_in, const int* in_sizes, int n_in,
                              void* d_out, int out_size)
{
    // Identify inputs by element count (robust to metadata ordering).
    const float *x = 0, *W1 = 0, *W2 = 0, *W21 = 0, *W22 = 0, *W3 = 0;
    const float *b1 = 0, *b2 = 0, *b21 = 0, *b22 = 0, *b3 = 0;
    int nhh = 0, nbb = 0;
    for (int i = 0; i < n_in; i++) {
        const float* p = (const float*)d_in[i];
        switch (in_sizes[i]) {
            case 8388608: x  = p; break;
            case 2097152: W1 = p; break;
            case 4259840: W3 = p; break;
            case 2080:    b3 = p; break;
            case 4194304:
                if      (nhh == 0) W2  = p;
                else if (nhh == 1) W21 = p;
                else               W22 = p;
                nhh++; break;
            case 2048:
                if      (nbb == 0) b1  = p;
                else if (nbb == 1) b2  = p;
                else if (nbb == 2) b21 = p;
                else               b22 = p;
                nbb++; break;
            default: break;
        }
    }

    void *pA0, *pA1, *pW1, *pW2, *pW21, *pW22, *pW3, *pY;
    cudaGetSymbolAddress(&pA0, g_A0);    cudaGetSymbolAddress(&pA1, g_A1);
    cudaGetSymbolAddress(&pW1, g_W1t);   cudaGetSymbolAddress(&pW2, g_W2t);
    cudaGetSymbolAddress(&pW21, g_W21t); cudaGetSymbolAddress(&pW22, g_W22t);
    cudaGetSymbolAddress(&pW3, g_W3t);   cudaGetSymbolAddress(&pY, g_Y);
    __half *A0 = (__half*)pA0, *A1 = (__half*)pA1;
    __half *W1t = (__half*)pW1, *W2t = (__half*)pW2;
    __half *W21t = (__half*)pW21, *W22t = (__half*)pW22, *W3t = (__half*)pW3;
    float* Y = (float*)pY;

    cudaFuncSetAttribute(gemm_f16,
                         cudaFuncAttributeMaxDynamicSharedMemorySize, SMEMSZ);

    dim3 tb(32, 8);
    dim3 blk(256);
    dim3 gH(HID / 256, BATCH / 128);                     // (8, 64)
    dim3 gL((LOUT + 255) / 256, BATCH / 128);            // (9, 64)

    cast_f32_f16<<<(BATCH * DIN / 4 + 255) / 256, 256>>>(x, A0, BATCH * DIN / 4);
    wsplit_t_kernel<<<dim3(HID / 32, DIN / 32), tb>>>(W1, W1t, DIN, HID);
    wsplit_t_kernel<<<dim3(HID / 32, HID / 32), tb>>>(W2, W2t, HID, HID);
    wsplit_t_kernel<<<dim3(HID / 32, HID / 32), tb>>>(W21, W21t, HID, HID);
    wsplit_t_kernel<<<dim3(HID / 32, HID / 32), tb>>>(W22, W22t, HID, HID);
    wsplit_t_kernel<<<dim3(LOUT / 32, HID / 32), tb>>>(W3, W3t, HID, LOUT);

    gemm_f16<<<gH, blk, SMEMSZ>>>(A0, W1t, b1, A1, 0, DIN, HID, 1, 0);
    gemm_f16<<<gH, blk, SMEMSZ>>>(A1, W2t, b2, A0, 0, HID, HID, 1, 0);
    gemm_f16<<<gH, blk, SMEMSZ>>>(A0, W21t, b21, A1, 0, HID, HID, 1, 0);
    gemm_f16<<<gH, blk, SMEMSZ>>>(A1, W22t, b22, A0, 0, HID, HID, 1, 0);
    gemm_f16<<<gL, blk, SMEMSZ>>>(A0, W3t, b3, 0, Y, HID, LOUT, 0, 1);

    dim3 gsc(LOUT / 32, BATCH / 32);
    dim3 bsc(32, 8);
    scatter_tri<<<gsc, bsc>>>(Y, (float*)d_out);   // includes lower-tri zeros
}